// round 1
// baseline (speedup 1.0000x reference)
#include <cuda_runtime.h>

// LaplacianReg: B=32, V=65536, K=8, C=3
// result[b,v,c] = (d[b,v,c] + sum_k w[v,k]*d[b,idx[v,k],c])^2  with d = out - tgt
//
// Pass 1: d -> transposed scratch (V,B,C) so neighbor gathers are coalesced.
// Pass 2: warp per v, lane per b; 8 coalesced 384B gather rows; smem-staged
//         transposed output write for full-sector stores.

#define BB 32
#define VV 65536
#define CC 3
#define KK 8

// 25.2 MB transposed diff scratch (v, b, c)
__device__ float g_diff[(size_t)VV * BB * CC];

// ---------------- Pass 1: diff + transpose ----------------
// flat over B*V*C elements, float4 vectorized reads (total % 4 == 0)
__global__ void __launch_bounds__(256) diff_transpose_kernel(
    const float* __restrict__ out_, const float* __restrict__ tgt_)
{
    int i4 = blockIdx.x * blockDim.x + threadIdx.x;  // 0 .. B*V*C/4-1
    const float4* o4 = (const float4*)out_;
    const float4* t4 = (const float4*)tgt_;
    float4 o = o4[i4];
    float4 t = t4[i4];
    float d[4] = { o.x - t.x, o.y - t.y, o.z - t.z, o.w - t.w };
    int base = i4 * 4;
#pragma unroll
    for (int j = 0; j < 4; j++) {
        int i = base + j;
        int b = i / (VV * CC);
        int r = i - b * (VV * CC);
        int v = r / CC;
        int c = r - v * CC;
        g_diff[(size_t)v * (BB * CC) + b * CC + c] = d[j];
    }
}

// ---------------- Pass 2: laplacian gather + square ----------------
// block = 256 threads = 8 warps; warp handles one v, lane = b.
__global__ void __launch_bounds__(256) lap_kernel(
    const int* __restrict__ nidx, const float* __restrict__ nw,
    float* __restrict__ res)
{
    __shared__ float s[8 * 100];  // [v_local][b][c], row padded 96->100 floats

    const int lane = threadIdx.x & 31;
    const int wrp  = threadIdx.x >> 5;
    const int v    = blockIdx.x * 8 + wrp;

    // lanes 0..7 hold the 8 (idx, weight) pairs; broadcast via shuffle
    int   n  = 0;
    float wk = 0.0f;
    if (lane < KK) {
        n  = nidx[v * KK + lane];
        wk = nw  [v * KK + lane];
    }

    const float* dv = g_diff + (size_t)v * (BB * CC) + lane * CC;
    float a0 = dv[0];
    float a1 = dv[1];
    float a2 = dv[2];

#pragma unroll
    for (int k = 0; k < KK; k++) {
        int   nk  = __shfl_sync(0xffffffffu, n,  k);
        float wkk = __shfl_sync(0xffffffffu, wk, k);
        const float* dn = g_diff + (size_t)nk * (BB * CC) + lane * CC;
        a0 = fmaf(wkk, dn[0], a0);
        a1 = fmaf(wkk, dn[1], a1);
        a2 = fmaf(wkk, dn[2], a2);
    }

    float* sw = s + wrp * 100 + lane * CC;
    sw[0] = a0 * a0;
    sw[1] = a1 * a1;
    sw[2] = a2 * a2;
    __syncthreads();

    // write out (B,V,C): thread tid -> b = tid/8, vl = tid%8, 3 floats.
    // per-warp: 4 contiguous 96B chunks -> full sector utilization.
    const int tid = threadIdx.x;
    const int b  = tid >> 3;
    const int vl = tid & 7;
    const int v0 = blockIdx.x * 8;
    const float* sr = s + vl * 100 + b * CC;
    float r0 = sr[0];
    float r1 = sr[1];
    float r2 = sr[2];
    float* op = res + (size_t)b * (VV * CC) + (v0 + vl) * CC;
    op[0] = r0;
    op[1] = r1;
    op[2] = r2;
}

extern "C" void kernel_launch(void* const* d_in, const int* in_sizes, int n_in,
                              void* d_out, int out_size)
{
    const float* out_ = (const float*)d_in[0];
    const float* tgt_ = (const float*)d_in[1];
    const int*   nidx = (const int*)  d_in[2];
    const float* nw   = (const float*)d_in[3];
    float*       res  = (float*)d_out;

    // Pass 1: B*V*C/4 = 1572864 threads
    diff_transpose_kernel<<<(BB * VV * CC / 4) / 256, 256>>>(out_, tgt_);

    // Pass 2: V/8 = 8192 blocks of 8 warps
    lap_kernel<<<VV / 8, 256>>>(nidx, nw, res);
}

// round 2
// speedup vs baseline: 1.4604x; 1.4604x over previous
#include <cuda_runtime.h>

// LaplacianReg: B=32, V=65536, K=8, C=3
// result[b,v,c] = (d[b,v,c] + sum_k w[v,k]*d[b,idx[v,k],c])^2,  d = out - tgt
//
// Scratch layout (v, c, b): one neighbor-row channel = 32 consecutive floats
// (128B) -> every gather LDG is exactly one cache line (1 L1 wavefront).

#define BB 32
#define VV 65536
#define CC 3
#define KK 8
#define ROW (BB * CC)      // 96 floats per v
#define TILE_V 64

// 25.2 MB transposed diff scratch, layout [v][c][b]
__device__ float g_diff[(size_t)VV * ROW];

// ---------------- Pass 1: diff + transpose (smem-staged, coalesced both ways)
// Block handles v-tile of 64: reads 64*3 floats per b (float4), transposes in
// smem to [v_local][c][b], writes 1536 float4 contiguous to g_diff.
__global__ void __launch_bounds__(256) diff_transpose_kernel(
    const float* __restrict__ out_, const float* __restrict__ tgt_)
{
    // padded rows: 96 -> 97 floats per v_local to break bank conflicts
    __shared__ float s[TILE_V * 97];

    const int tid = threadIdx.x;
    const int v0  = blockIdx.x * TILE_V;

    // read: 1536 float4 per input (32 b x 48 float4 each)
#pragma unroll
    for (int it = 0; it < 6; it++) {
        int r4   = tid + it * 256;          // 0..1535
        int b    = r4 / 48;
        int off4 = r4 - b * 48;             // float4 index within this b's 192-float chunk
        const float* obase = out_ + (size_t)b * (VV * CC) + v0 * CC;
        const float* tbase = tgt_ + (size_t)b * (VV * CC) + v0 * CC;
        float4 o = ((const float4*)obase)[off4];
        float4 t = ((const float4*)tbase)[off4];
        float d[4] = { o.x - t.x, o.y - t.y, o.z - t.z, o.w - t.w };
        int off = off4 * 4;                 // element offset 0..191 = v_local*3 + c
#pragma unroll
        for (int j = 0; j < 4; j++) {
            int oo = off + j;
            int vl = oo / 3;
            int c  = oo - vl * 3;
            s[vl * 97 + c * 32 + b] = d[j];
        }
    }
    __syncthreads();

    // write: 1536 contiguous float4 into g_diff tile
    float* gout = g_diff + (size_t)v0 * ROW;
#pragma unroll
    for (int it = 0; it < 6; it++) {
        int f4   = tid + it * 256;
        int flat = f4 * 4;                  // 0..6143, = v_local*96 + c*32 + b
        float4 w;
        {
            int i0 = flat;     int a0 = (i0 / 96) * 97 + (i0 % 96);
            int i1 = flat + 1; int a1 = (i1 / 96) * 97 + (i1 % 96);
            int i2 = flat + 2; int a2 = (i2 / 96) * 97 + (i2 % 96);
            int i3 = flat + 3; int a3 = (i3 / 96) * 97 + (i3 % 96);
            w.x = s[a0]; w.y = s[a1]; w.z = s[a2]; w.w = s[a3];
        }
        ((float4*)gout)[f4] = w;
    }
}

// ---------------- Pass 2: laplacian gather + square ----------------
// block = 256 threads = 8 warps; warp handles one v, lane = b.
// every g_diff load: 32 lanes x 4B consecutive = exactly 1 line.
__global__ void __launch_bounds__(256) lap_kernel(
    const int* __restrict__ nidx, const float* __restrict__ nw,
    float* __restrict__ res)
{
    __shared__ float s[8 * 100];  // [v_local][b*3+c], row padded 96->100

    const int lane = threadIdx.x & 31;
    const int wrp  = threadIdx.x >> 5;
    const int v    = blockIdx.x * 8 + wrp;

    // lanes 0..7 hold the 8 (idx, weight) pairs; broadcast via shuffle
    int   n  = 0;
    float wk = 0.0f;
    if (lane < KK) {
        n  = nidx[v * KK + lane];
        wk = nw  [v * KK + lane];
    }

    const float* dv = g_diff + v * ROW + lane;
    float a0 = dv[0];
    float a1 = dv[32];
    float a2 = dv[64];

#pragma unroll
    for (int k = 0; k < KK; k++) {
        int   nk  = __shfl_sync(0xffffffffu, n,  k);
        float wkk = __shfl_sync(0xffffffffu, wk, k);
        const float* dn = g_diff + nk * ROW + lane;
        a0 = fmaf(wkk, dn[0],  a0);
        a1 = fmaf(wkk, dn[32], a1);
        a2 = fmaf(wkk, dn[64], a2);
    }

    // stage squared result as [v_local][b][c] for coalesced (B,V,C) writes
    float* sw = s + wrp * 100 + lane * 3;
    sw[0] = a0 * a0;
    sw[1] = a1 * a1;
    sw[2] = a2 * a2;
    __syncthreads();

    const int tid = threadIdx.x;
    const int b   = tid >> 3;
    const int vl  = tid & 7;
    const int v0  = blockIdx.x * 8;
    const float* sr = s + vl * 100 + b * 3;
    float r0 = sr[0];
    float r1 = sr[1];
    float r2 = sr[2];
    float* op = res + (size_t)b * (VV * CC) + (v0 + vl) * CC;
    op[0] = r0;
    op[1] = r1;
    op[2] = r2;
}

extern "C" void kernel_launch(void* const* d_in, const int* in_sizes, int n_in,
                              void* d_out, int out_size)
{
    const float* out_ = (const float*)d_in[0];
    const float* tgt_ = (const float*)d_in[1];
    const int*   nidx = (const int*)  d_in[2];
    const float* nw   = (const float*)d_in[3];
    float*       res  = (float*)d_out;

    diff_transpose_kernel<<<VV / TILE_V, 256>>>(out_, tgt_);
    lap_kernel<<<VV / 8, 256>>>(nidx, nw, res);
}

// round 3
// speedup vs baseline: 1.9652x; 1.3457x over previous
#include <cuda_runtime.h>
#include <cuda_fp16.h>

// LaplacianReg: B=32, V=65536, K=8, C=3
// result[b,v,c] = (d[b,v,c] + sum_k w[v,k]*d[b,idx[v,k],c])^2,  d = out - tgt
//
// fp16 scratch in layout [v][c][b] (96 halfs = 192B per v) halves the L2
// gather traffic (the measured bottleneck). fp32 accumulation.

#define BB 32
#define VV 65536
#define CC 3
#define KK 8
#define ROWH 96        // halfs per v
#define TILE_V 64
#define P1PAD 104      // pass-1 smem halfs per v row (16B-aligned rows)
#define P2PAD 108      // pass-2 smem floats per v row (conflict-free + 16B-aligned)

// 12.6 MB fp16 scratch, declared as uint4 for guaranteed 16B alignment
__device__ uint4 g_diff_raw[(size_t)VV * ROWH * 2 / 16];

// ---------------- Pass 1: diff + fp16 convert + transpose ----------------
__global__ void __launch_bounds__(256) diff_transpose_kernel(
    const float* __restrict__ out_, const float* __restrict__ tgt_)
{
    __shared__ __half s[TILE_V * P1PAD];

    const int tid = threadIdx.x;
    const int v0  = blockIdx.x * TILE_V;

    // read: 1536 float4 per input (32 b x 48 float4 each), coalesced
#pragma unroll
    for (int it = 0; it < 6; it++) {
        int r4   = tid + it * 256;          // 0..1535
        int b    = r4 / 48;
        int off4 = r4 - b * 48;
        const float4* o4 = (const float4*)(out_ + (size_t)b * (VV * CC) + (size_t)v0 * CC);
        const float4* t4 = (const float4*)(tgt_ + (size_t)b * (VV * CC) + (size_t)v0 * CC);
        float4 o = o4[off4];
        float4 t = t4[off4];
        float d[4] = { o.x - t.x, o.y - t.y, o.z - t.z, o.w - t.w };
        int off = off4 * 4;                 // 0..191 = v_local*3 + c
#pragma unroll
        for (int j = 0; j < 4; j++) {
            int oo = off + j;
            int vl = oo / 3;
            int c  = oo - vl * 3;
            s[vl * P1PAD + c * 32 + b] = __float2half_rn(d[j]);
        }
    }
    __syncthreads();

    // write: 768 uint4 (16B = 8 halfs) contiguous into g_diff tile
    uint4* gout = g_diff_raw + (size_t)v0 * ROWH / 8;
#pragma unroll
    for (int it = 0; it < 3; it++) {
        int f    = tid + it * 256;          // 0..767
        int flat = f * 8;                   // half index within tile, 96 % 8 == 0
        int vl   = flat / 96;
        int off  = flat - vl * 96;
        uint4 w = *(const uint4*)(s + vl * P1PAD + off);
        gout[f] = w;
    }
}

// ---------------- Pass 2: laplacian gather + square ----------------
// warp per v; lanes 0..23 each load 4 consecutive halfs (LDG.64) -> one
// instruction covers the whole 192B row.
__global__ void __launch_bounds__(256) lap_kernel(
    const int* __restrict__ nidx, const float* __restrict__ nw,
    float* __restrict__ res)
{
    __shared__ float s[8 * P2PAD];
    __shared__ int   si[64];
    __shared__ float swt[64];

    const int tid  = threadIdx.x;
    const int lane = tid & 31;
    const int wrp  = tid >> 5;
    const int v0   = blockIdx.x * 8;
    const int v    = v0 + wrp;

    if (tid < 64)        si[tid]       = nidx[v0 * KK + tid];
    else if (tid < 128)  swt[tid - 64] = nw[v0 * KK + (tid - 64)];
    __syncthreads();

    const __half* gd = (const __half*)g_diff_raw;

    if (lane < 24) {
        // self row, weight 1
        uint2 raw = *(const uint2*)(gd + (size_t)v * ROWH + lane * 4);
        float2 f01 = __half22float2(*(const __half2*)&raw.x);
        float2 f23 = __half22float2(*(const __half2*)&raw.y);
        float a0 = f01.x, a1 = f01.y, a2 = f23.x, a3 = f23.y;

#pragma unroll
        for (int k = 0; k < KK; k++) {
            int   nk = si[wrp * KK + k];
            float wk = swt[wrp * KK + k];
            uint2 r  = *(const uint2*)(gd + (size_t)nk * ROWH + lane * 4);
            float2 g01 = __half22float2(*(const __half2*)&r.x);
            float2 g23 = __half22float2(*(const __half2*)&r.y);
            a0 = fmaf(wk, g01.x, a0);
            a1 = fmaf(wk, g01.y, a1);
            a2 = fmaf(wk, g23.x, a2);
            a3 = fmaf(wk, g23.y, a3);
        }

        // stage squared result; flat = lane*4+j = c*32+b
        float4 sq;
        sq.x = a0 * a0;
        sq.y = a1 * a1;
        sq.z = a2 * a2;
        sq.w = a3 * a3;
        *(float4*)(s + wrp * P2PAD + lane * 4) = sq;
    }
    __syncthreads();

    // output (B,V,C): thread -> b = tid/8, vl = tid%8; res[b][v0+vl][c] = s[vl][c*32+b]
    const int b  = tid >> 3;
    const int vl = tid & 7;
    const float* sr = s + vl * P2PAD + b;
    float r0 = sr[0];
    float r1 = sr[32];
    float r2 = sr[64];
    float* op = res + (size_t)b * (VV * CC) + (size_t)(v0 + vl) * CC;
    op[0] = r0;
    op[1] = r1;
    op[2] = r2;
}

extern "C" void kernel_launch(void* const* d_in, const int* in_sizes, int n_in,
                              void* d_out, int out_size)
{
    const float* out_ = (const float*)d_in[0];
    const float* tgt_ = (const float*)d_in[1];
    const int*   nidx = (const int*)  d_in[2];
    const float* nw   = (const float*)d_in[3];
    float*       res  = (float*)d_out;

    diff_transpose_kernel<<<VV / TILE_V, 256>>>(out_, tgt_);
    lap_kernel<<<VV / 8, 256>>>(nidx, nw, res);
}